// round 3
// baseline (speedup 1.0000x reference)
#include <cuda_runtime.h>

#define NN 50000
#define NE 1600000
#define NB_NODE 196              // ceil(NN/256)

typedef unsigned long long ull;

struct __align__(8) EP { int s; float w; };

// ---------------- scratch (device globals; no allocations) ----------------
__device__ float g_degW[NN];
__device__ float g_dinv[NN];
__device__ int   g_cnt[NN];
__device__ int   g_bsum[NB_NODE];
__device__ int   g_boff[NB_NODE];
__device__ int   g_total;
__device__ int   g_rowptr[NN + 1];
__device__ int   g_wp[NN];
__device__ __align__(16) EP g_ep[NE];
__device__ __align__(16) float g_TX[4][NN * 32];       // Tx1..Tx4
__device__ __align__(16) float g_h[NN * 32];           // layer-1 output
__device__ __align__(16) float2 g_Wq[2][96 * 164];     // splatted {w,w} weights, row pad 164
__device__ float g_bp[2][96];                          // folded biases
__device__ __align__(16) float g_weff[32];             // folded head weight
__device__ float g_beff;

__device__ __forceinline__ const float* sel_ptr(int sel, const float* xext) {
    if (sel == 9) return xext;
    if (sel == 4) return g_h;
    return g_TX[sel];
}

__device__ __forceinline__ float fsig(float x) { return 1.f / (1.f + __expf(-x)); }
__device__ __forceinline__ float ftanh(float x) {
    x = fminf(fmaxf(x, -15.f), 15.f);
    float t = __expf(2.f * x);
    return (t - 1.f) / (t + 1.f);
}

// ---- packed f32x2 helpers (sm_103a FFMA2 is PTX-only) ----
__device__ __forceinline__ ull pk2(float lo, float hi) {
    ull r; asm("mov.b64 %0, {%1, %2};" : "=l"(r) : "f"(lo), "f"(hi)); return r;
}
__device__ __forceinline__ ull ffma2(ull a, ull b, ull c) {
    ull d; asm("fma.rn.f32x2 %0, %1, %2, %3;" : "=l"(d) : "l"(a), "l"(b), "l"(c)); return d;
}
__device__ __forceinline__ void upk2(ull v, float& lo, float& hi) {
    asm("mov.b64 {%0, %1}, %2;" : "=f"(lo), "=f"(hi) : "l"(v));
}

// ---------------- CSR build ----------------
__global__ void k_zero() {
    int i = blockIdx.x * blockDim.x + threadIdx.x;
    if (i < NN) { g_degW[i] = 0.f; g_cnt[i] = 0; }
}

__global__ void k_degree(const int* __restrict__ ei, const float* __restrict__ ew) {
    int e = blockIdx.x * blockDim.x + threadIdx.x;
    if (e >= NE) return;
    atomicAdd(&g_degW[ei[e]], ew[e]);       // weighted deg by SRC
    atomicAdd(&g_cnt[ei[NE + e]], 1);       // in-degree by DST
}

// dinv + per-block count sums (fused)
__global__ void k_dinvsum() {
    __shared__ int sh[256];
    int t = threadIdx.x;
    int i = blockIdx.x * 256 + t;
    int c = 0;
    if (i < NN) {
        float d = g_degW[i];
        g_dinv[i] = (d > 0.f) ? rsqrtf(fmaxf(d, 1e-12f)) : 0.f;
        c = g_cnt[i];
    }
    sh[t] = c;
    __syncthreads();
    for (int off = 128; off > 0; off >>= 1) {
        if (t < off) sh[t] += sh[t + off];
        __syncthreads();
    }
    if (t == 0) g_bsum[blockIdx.x] = sh[0];
}

__global__ void k_scanb() {   // single block: scan NB_NODE block sums
    __shared__ int sh[256];
    int t = threadIdx.x;
    sh[t] = (t < NB_NODE) ? g_bsum[t] : 0;
    __syncthreads();
    for (int off = 1; off < 256; off <<= 1) {
        int v = 0;
        if (t >= off) v = sh[t - off];
        __syncthreads();
        sh[t] += v;
        __syncthreads();
    }
    if (t < NB_NODE) g_boff[t] = (t == 0) ? 0 : sh[t - 1];
    if (t == NB_NODE - 1) g_total = sh[t];
}

__global__ void k_rowptr() {  // per-block local scan + global offset
    __shared__ int sh[256];
    int t = threadIdx.x;
    int i = blockIdx.x * 256 + t;
    int c = (i < NN) ? g_cnt[i] : 0;
    sh[t] = c;
    __syncthreads();
    for (int off = 1; off < 256; off <<= 1) {
        int v = 0;
        if (t >= off) v = sh[t - off];
        __syncthreads();
        sh[t] += v;
        __syncthreads();
    }
    if (i < NN) {
        int rp = g_boff[blockIdx.x] + sh[t] - c;   // exclusive
        g_rowptr[i] = rp;
        g_wp[i] = rp;
    }
    if (i == NN) g_rowptr[NN] = g_total;
}

__global__ void k_scatter(const int* __restrict__ ei, const float* __restrict__ ew) {
    int e = blockIdx.x * blockDim.x + threadIdx.x;
    if (e >= NE) return;
    int s = ei[e], d = ei[NE + e];
    int pos = atomicAdd(&g_wp[d], 1);
    EP p;
    p.s = s;
    p.w = -g_dinv[s] * ew[e] * g_dinv[d];
    g_ep[pos] = p;
}

// ---------------- weight / head prep ----------------
__global__ void k_prepw(const float* __restrict__ Wx, const float* __restrict__ bx,
                        const float* __restrict__ bh, const float* __restrict__ bb,
                        int layer) {
    int idx = blockIdx.x * blockDim.x + threadIdx.x;
    if (idx >= 96 * 160) return;
    int o = idx / 160, j = idx % 160;
    int gi = o >> 5, f = o & 31;
    int g = (gi == 0) ? 0 : ((gi == 1) ? 2 : 3);   // gates i, c, o (forget dead: C=0)
    int k = j >> 5, jj = j & 31;
    float w = Wx[(((g * 5 + k) * 32) + jj) * 32 + f];
    g_Wq[layer][o * 164 + j] = make_float2(w, w);  // splatted pair
    if (j == 0) g_bp[layer][o] = bx[g * 32 + f] + bh[g * 32 + f] + bb[g * 32 + f];
}

__global__ void k_headfold(const float* __restrict__ hw1, const float* __restrict__ hb1,
                           const float* __restrict__ hw2, const float* __restrict__ hb2,
                           const float* __restrict__ hw3, const float* __restrict__ hb3,
                           const float* __restrict__ hw4, const float* __restrict__ hb4) {
    int r = threadIdx.x;   // 32 threads
    float t1r[16], t2r[8], t3r[4];
    for (int c = 0; c < 16; c++) t1r[c] = hw1[r * 16 + c];
    for (int c = 0; c < 8; c++) {
        float s = 0.f;
        for (int i = 0; i < 16; i++) s += t1r[i] * hw2[i * 8 + c];
        t2r[c] = s;
    }
    for (int c = 0; c < 4; c++) {
        float s = 0.f;
        for (int i = 0; i < 8; i++) s += t2r[i] * hw3[i * 4 + c];
        t3r[c] = s;
    }
    float we = 0.f;
    for (int i = 0; i < 4; i++) we += t3r[i] * hw4[i];
    g_weff[r] = we;
    if (r == 0) {
        float v2[8], v3[4];
        for (int c = 0; c < 8; c++) {
            float s = hb2[c];
            for (int i = 0; i < 16; i++) s += hb1[i] * hw2[i * 8 + c];
            v2[c] = s;
        }
        for (int c = 0; c < 4; c++) {
            float s = hb3[c];
            for (int i = 0; i < 8; i++) s += v2[i] * hw3[i * 4 + c];
            v3[c] = s;
        }
        float b = hb4[0];
        for (int i = 0; i < 4; i++) b += v3[i] * hw4[i];
        g_beff = b;
    }
}

// ---------------- sparse propagation ----------------
template <bool SUB>
__global__ void k_prop(const float* __restrict__ xext, int insel, int prevsel, int outsel) {
    int gw = (blockIdx.x * blockDim.x + threadIdx.x) >> 5;
    int lane = threadIdx.x & 31;
    if (gw >= NN) return;
    const float* xin = sel_ptr(insel, xext);
    int beg = g_rowptr[gw], end = g_rowptr[gw + 1];
    float acc = 0.f;
    int e = beg;
    if ((e & 1) && e < end) {                       // align to EP-pair boundary
        EP p = g_ep[e];
        acc = fmaf(p.w, xin[p.s * 32 + lane], acc);
        e++;
    }
    const uint4* ep2 = (const uint4*)g_ep;          // 2 EPs per 16B load
#pragma unroll 1
    for (; e + 4 <= end; e += 4) {
        uint4 a = ep2[e >> 1];
        uint4 b = ep2[(e >> 1) + 1];
        float x0 = xin[(int)a.x * 32 + lane];
        float x1 = xin[(int)a.z * 32 + lane];
        float x2 = xin[(int)b.x * 32 + lane];
        float x3 = xin[(int)b.z * 32 + lane];
        acc = fmaf(__uint_as_float(a.y), x0, acc);
        acc = fmaf(__uint_as_float(a.w), x1, acc);
        acc = fmaf(__uint_as_float(b.y), x2, acc);
        acc = fmaf(__uint_as_float(b.w), x3, acc);
    }
    if (e + 2 <= end) {
        uint4 a = ep2[e >> 1];
        acc = fmaf(__uint_as_float(a.y), xin[(int)a.x * 32 + lane], acc);
        acc = fmaf(__uint_as_float(a.w), xin[(int)a.z * 32 + lane], acc);
        e += 2;
    }
    if (e < end) {
        EP p = g_ep[e];
        acc = fmaf(p.w, xin[p.s * 32 + lane], acc);
    }
    int o = gw * 32 + lane;
    if (SUB) {
        const float* prev = sel_ptr(prevsel, xext);
        g_TX[outsel][o] = 2.f * acc - prev[o];
    } else {
        g_TX[outsel][o] = acc;
    }
}

// ---------------- fused Chebyshev GEMM + gates (+ head for MODE 1) ----------------
// MODE 0: write relu(h) to g_h.   MODE 1: fold head, write out[n].
template <int MODE>
__global__ void __launch_bounds__(128) k_gemm(const float* __restrict__ xext, int insel,
                                              int layer, const float* __restrict__ wc,
                                              float* __restrict__ out) {
    int w = threadIdx.x >> 5, lane = threadIdx.x & 31;
    int n0 = blockIdx.x * 16 + w * 4;
    const float* planes[5] = {sel_ptr(insel, xext), g_TX[0], g_TX[1], g_TX[2], g_TX[3]};
    const float2* W = g_Wq[layer];
    const float* bp = g_bp[layer];
    float b0 = bp[lane], b1 = bp[lane + 32], b2 = bp[lane + 64];
    ull acc[2][3];
#pragma unroll
    for (int tp = 0; tp < 2; tp++) {
        acc[tp][0] = pk2(b0, b0);
        acc[tp][1] = pk2(b1, b1);
        acc[tp][2] = pk2(b2, b2);
    }
    const float2* Wr0 = W + lane * 164;
    const float2* Wr1 = W + (lane + 32) * 164;
    const float2* Wr2 = W + (lane + 64) * 164;
#pragma unroll
    for (int k = 0; k < 5; k++) {
        const float* pl = planes[k];
#pragma unroll
        for (int jj = 0; jj < 32; jj += 4) {
            int j = k * 32 + jj;
            ulonglong2 wA0 = *(const ulonglong2*)(Wr0 + j);
            ulonglong2 wB0 = *(const ulonglong2*)(Wr0 + j + 2);
            ulonglong2 wA1 = *(const ulonglong2*)(Wr1 + j);
            ulonglong2 wB1 = *(const ulonglong2*)(Wr1 + j + 2);
            ulonglong2 wA2 = *(const ulonglong2*)(Wr2 + j);
            ulonglong2 wB2 = *(const ulonglong2*)(Wr2 + j + 2);
            float4 x0 = *(const float4*)(pl + (n0 + 0) * 32 + jj);
            float4 x1 = *(const float4*)(pl + (n0 + 1) * 32 + jj);
            float4 x2 = *(const float4*)(pl + (n0 + 2) * 32 + jj);
            float4 x3 = *(const float4*)(pl + (n0 + 3) * 32 + jj);
            ull xx0[4] = {pk2(x0.x, x1.x), pk2(x0.y, x1.y), pk2(x0.z, x1.z), pk2(x0.w, x1.w)};
            ull xx1[4] = {pk2(x2.x, x3.x), pk2(x2.y, x3.y), pk2(x2.z, x3.z), pk2(x2.w, x3.w)};
            ull w0[4] = {wA0.x, wA0.y, wB0.x, wB0.y};
            ull w1[4] = {wA1.x, wA1.y, wB1.x, wB1.y};
            ull w2[4] = {wA2.x, wA2.y, wB2.x, wB2.y};
#pragma unroll
            for (int c = 0; c < 4; c++) {
                acc[0][0] = ffma2(xx0[c], w0[c], acc[0][0]);
                acc[1][0] = ffma2(xx1[c], w0[c], acc[1][0]);
                acc[0][1] = ffma2(xx0[c], w1[c], acc[0][1]);
                acc[1][1] = ffma2(xx1[c], w1[c], acc[1][1]);
                acc[0][2] = ffma2(xx0[c], w2[c], acc[0][2]);
                acc[1][2] = ffma2(xx1[c], w2[c], acc[1][2]);
            }
        }
    }
    // ---- epilogue: gates (i, c, o), H=C=0 GConvLSTM ----
    float wc2 = wc[64 + lane];
    float we = 0.f, be = 0.f;
    if (MODE == 1) { we = g_weff[lane]; be = g_beff; }
#pragma unroll
    for (int tp = 0; tp < 2; tp++) {
        float iv[2], cv[2], ov[2];
        upk2(acc[tp][0], iv[0], iv[1]);
        upk2(acc[tp][1], cv[0], cv[1]);
        upk2(acc[tp][2], ov[0], ov[1]);
#pragma unroll
        for (int u = 0; u < 2; u++) {
            int n = n0 + tp * 2 + u;
            float I  = fsig(iv[u]);
            float Cn = I * ftanh(cv[u]);
            float O  = fsig(ov[u] + wc2 * Cn);
            float h  = fmaxf(O * ftanh(Cn), 0.f);
            if (MODE == 0) {
                g_h[n * 32 + lane] = h;
            } else {
                float v = h * we;
#pragma unroll
                for (int off = 16; off > 0; off >>= 1)
                    v += __shfl_xor_sync(0xffffffffu, v, off);
                if (lane == 0) out[n] = v + be;
            }
        }
    }
}

// ---------------- launch ----------------
extern "C" void kernel_launch(void* const* d_in, const int* in_sizes, int n_in,
                              void* d_out, int out_size) {
    const float* x     = (const float*)d_in[0];
    const int*   ei    = (const int*)d_in[1];
    const float* ew    = (const float*)d_in[2];
    const float* l1_Wx = (const float*)d_in[3];
    const float* l1_bx = (const float*)d_in[4];
    const float* l1_bh = (const float*)d_in[6];
    const float* l1_wc = (const float*)d_in[7];
    const float* l1_b  = (const float*)d_in[8];
    const float* l2_Wx = (const float*)d_in[9];
    const float* l2_bx = (const float*)d_in[10];
    const float* l2_bh = (const float*)d_in[12];
    const float* l2_wc = (const float*)d_in[13];
    const float* l2_b  = (const float*)d_in[14];
    const float* hw1   = (const float*)d_in[15];
    const float* hb1   = (const float*)d_in[16];
    const float* hw2   = (const float*)d_in[17];
    const float* hb2   = (const float*)d_in[18];
    const float* hw3   = (const float*)d_in[19];
    const float* hb3   = (const float*)d_in[20];
    const float* hw4   = (const float*)d_in[21];
    const float* hb4   = (const float*)d_in[22];
    float* out = (float*)d_out;

    const int NB_E = (NE + 255) / 256;   // 6250
    const int NB_W = 6250;               // 50000 warps / 8
    const int NB_G = NN / 16;            // 3125

    // graph normalization + CSR (hierarchical scan, no single-block bottleneck)
    k_zero<<<NB_NODE, 256>>>();
    k_degree<<<NB_E, 256>>>(ei, ew);
    k_dinvsum<<<NB_NODE, 256>>>();
    k_scanb<<<1, 256>>>();
    k_rowptr<<<NB_NODE, 256>>>();
    k_scatter<<<NB_E, 256>>>(ei, ew);

    // weight packing + head folding
    k_prepw<<<60, 256>>>(l1_Wx, l1_bx, l1_bh, l1_b, 0);
    k_prepw<<<60, 256>>>(l2_Wx, l2_bx, l2_bh, l2_b, 1);
    k_headfold<<<1, 32>>>(hw1, hb1, hw2, hb2, hw3, hb3, hw4, hb4);

    // layer 1 (input = x, sel 9) -> g_h
    k_prop<false><<<NB_W, 256>>>(x, 9, -1, 0);
    k_prop<true ><<<NB_W, 256>>>(x, 0, 9, 1);
    k_prop<true ><<<NB_W, 256>>>(x, 1, 0, 2);
    k_prop<true ><<<NB_W, 256>>>(x, 2, 1, 3);
    k_gemm<0><<<NB_G, 128>>>(x, 9, 0, l1_wc, out);

    // layer 2 (input = g_h, sel 4) -> out (head fused)
    k_prop<false><<<NB_W, 256>>>(x, 4, -1, 0);
    k_prop<true ><<<NB_W, 256>>>(x, 0, 4, 1);
    k_prop<true ><<<NB_W, 256>>>(x, 1, 0, 2);
    k_prop<true ><<<NB_W, 256>>>(x, 2, 1, 3);
    k_gemm<1><<<NB_G, 128>>>(x, 4, 1, l2_wc, out);
}

// round 4
// speedup vs baseline: 1.3236x; 1.3236x over previous
#include <cuda_runtime.h>

#define NN 50000
#define NE 1600000
#define NB_NODE 196              // ceil(NN/256)

typedef unsigned long long ull;

struct __align__(8) EP { int s; float w; };

// ---------------- scratch (device globals; no allocations) ----------------
__device__ float g_degW[NN];
__device__ float g_dinv[NN];
__device__ int   g_cnt[NN];
__device__ int   g_bsum[NB_NODE];
__device__ int   g_boff[NB_NODE];
__device__ int   g_total;
__device__ int   g_rowptr[NN + 1];
__device__ int   g_wp[NN];
__device__ __align__(16) EP g_ep[NE];
__device__ __align__(16) float g_TX[4][NN * 32];       // Tx1..Tx4
__device__ __align__(16) float g_h[NN * 32];           // layer-1 output
__device__ __align__(16) float4 g_Wj[2][80 * 96];      // j-major splatted weights: [j/2][96] of {wj,wj,wj1,wj1}
__device__ float g_bp[2][96];                          // folded biases
__device__ __align__(16) float g_weff[32];             // folded head weight
__device__ float g_beff;

__device__ __forceinline__ const float* sel_ptr(int sel, const float* xext) {
    if (sel == 9) return xext;
    if (sel == 4) return g_h;
    return g_TX[sel];
}

__device__ __forceinline__ float fsig(float x) { return 1.f / (1.f + __expf(-x)); }
__device__ __forceinline__ float ftanh(float x) {
    x = fminf(fmaxf(x, -15.f), 15.f);
    float t = __expf(2.f * x);
    return (t - 1.f) / (t + 1.f);
}

// ---- packed f32x2 helpers (sm_103a FFMA2 is PTX-only) ----
__device__ __forceinline__ ull pk2(float lo, float hi) {
    ull r; asm("mov.b64 %0, {%1, %2};" : "=l"(r) : "f"(lo), "f"(hi)); return r;
}
__device__ __forceinline__ ull ffma2(ull a, ull b, ull c) {
    ull d; asm("fma.rn.f32x2 %0, %1, %2, %3;" : "=l"(d) : "l"(a), "l"(b), "l"(c)); return d;
}
__device__ __forceinline__ void upk2(ull v, float& lo, float& hi) {
    asm("mov.b64 {%0, %1}, %2;" : "=f"(lo), "=f"(hi) : "l"(v));
}

// ---------------- CSR build ----------------
__global__ void k_zero() {
    int i = blockIdx.x * blockDim.x + threadIdx.x;
    if (i < NN) { g_degW[i] = 0.f; g_cnt[i] = 0; }
}

__global__ void k_degree(const int* __restrict__ ei, const float* __restrict__ ew) {
    int e = blockIdx.x * blockDim.x + threadIdx.x;
    if (e >= NE) return;
    atomicAdd(&g_degW[ei[e]], ew[e]);       // weighted deg by SRC
    atomicAdd(&g_cnt[ei[NE + e]], 1);       // in-degree by DST
}

__global__ void k_dinvsum() {               // dinv + per-block count sums
    __shared__ int sh[256];
    int t = threadIdx.x;
    int i = blockIdx.x * 256 + t;
    int c = 0;
    if (i < NN) {
        float d = g_degW[i];
        g_dinv[i] = (d > 0.f) ? rsqrtf(fmaxf(d, 1e-12f)) : 0.f;
        c = g_cnt[i];
    }
    sh[t] = c;
    __syncthreads();
    for (int off = 128; off > 0; off >>= 1) {
        if (t < off) sh[t] += sh[t + off];
        __syncthreads();
    }
    if (t == 0) g_bsum[blockIdx.x] = sh[0];
}

__global__ void k_scanb() {                 // single block: scan block sums
    __shared__ int sh[256];
    int t = threadIdx.x;
    sh[t] = (t < NB_NODE) ? g_bsum[t] : 0;
    __syncthreads();
    for (int off = 1; off < 256; off <<= 1) {
        int v = 0;
        if (t >= off) v = sh[t - off];
        __syncthreads();
        sh[t] += v;
        __syncthreads();
    }
    if (t < NB_NODE) g_boff[t] = (t == 0) ? 0 : sh[t - 1];
    if (t == NB_NODE - 1) g_total = sh[t];
}

__global__ void k_rowptr() {                // per-block local scan + offset
    __shared__ int sh[256];
    int t = threadIdx.x;
    int i = blockIdx.x * 256 + t;
    int c = (i < NN) ? g_cnt[i] : 0;
    sh[t] = c;
    __syncthreads();
    for (int off = 1; off < 256; off <<= 1) {
        int v = 0;
        if (t >= off) v = sh[t - off];
        __syncthreads();
        sh[t] += v;
        __syncthreads();
    }
    if (i < NN) {
        int rp = g_boff[blockIdx.x] + sh[t] - c;
        g_rowptr[i] = rp;
        g_wp[i] = rp;
    }
    if (i == NN) g_rowptr[NN] = g_total;
}

__global__ void k_scatter(const int* __restrict__ ei, const float* __restrict__ ew) {
    int e = blockIdx.x * blockDim.x + threadIdx.x;
    if (e >= NE) return;
    int s = ei[e], d = ei[NE + e];
    int pos = atomicAdd(&g_wp[d], 1);
    EP p;
    p.s = s;
    p.w = -g_dinv[s] * ew[e] * g_dinv[d];
    g_ep[pos] = p;
}

// ---------------- weight / head prep ----------------
// pack j-major splatted pairs: g_Wj[layer][j2*96 + o] = {w(2j2,o), w(2j2,o), w(2j2+1,o), w(2j2+1,o)}
__global__ void k_prepw(const float* __restrict__ Wx, const float* __restrict__ bx,
                        const float* __restrict__ bh, const float* __restrict__ bb,
                        int layer) {
    int idx = blockIdx.x * blockDim.x + threadIdx.x;
    if (idx >= 80 * 96) return;
    int j2 = idx / 96, o = idx % 96;
    int gi = o >> 5, f = o & 31;
    int g = (gi == 0) ? 0 : ((gi == 1) ? 2 : 3);   // gates i, c, o (forget dead: C=0)
    float w[2];
#pragma unroll
    for (int u = 0; u < 2; u++) {
        int j = 2 * j2 + u;
        int k = j >> 5, jj = j & 31;
        w[u] = Wx[(((g * 5 + k) * 32) + jj) * 32 + f];
    }
    g_Wj[layer][idx] = make_float4(w[0], w[0], w[1], w[1]);
    if (j2 == 0) g_bp[layer][o] = bx[g * 32 + f] + bh[g * 32 + f] + bb[g * 32 + f];
}

__global__ void k_headfold(const float* __restrict__ hw1, const float* __restrict__ hb1,
                           const float* __restrict__ hw2, const float* __restrict__ hb2,
                           const float* __restrict__ hw3, const float* __restrict__ hb3,
                           const float* __restrict__ hw4, const float* __restrict__ hb4) {
    int r = threadIdx.x;   // 32 threads
    float t1r[16], t2r[8], t3r[4];
    for (int c = 0; c < 16; c++) t1r[c] = hw1[r * 16 + c];
    for (int c = 0; c < 8; c++) {
        float s = 0.f;
        for (int i = 0; i < 16; i++) s += t1r[i] * hw2[i * 8 + c];
        t2r[c] = s;
    }
    for (int c = 0; c < 4; c++) {
        float s = 0.f;
        for (int i = 0; i < 8; i++) s += t2r[i] * hw3[i * 4 + c];
        t3r[c] = s;
    }
    float we = 0.f;
    for (int i = 0; i < 4; i++) we += t3r[i] * hw4[i];
    g_weff[r] = we;
    if (r == 0) {
        float v2[8], v3[4];
        for (int c = 0; c < 8; c++) {
            float s = hb2[c];
            for (int i = 0; i < 16; i++) s += hb1[i] * hw2[i * 8 + c];
            v2[c] = s;
        }
        for (int c = 0; c < 4; c++) {
            float s = hb3[c];
            for (int i = 0; i < 8; i++) s += v2[i] * hw3[i * 4 + c];
            v3[c] = s;
        }
        float b = hb4[0];
        for (int i = 0; i < 4; i++) b += v3[i] * hw4[i];
        g_beff = b;
    }
}

// ---------------- sparse propagation: 4 edges/warp, 8 lanes x float4 per edge ----------------
template <bool SUB>
__global__ void k_prop(const float* __restrict__ xext, int insel, int prevsel, int outsel) {
    int gw = (blockIdx.x * blockDim.x + threadIdx.x) >> 5;
    int lane = threadIdx.x & 31;
    if (gw >= NN) return;
    const float* xin = sel_ptr(insel, xext);
    int grp = lane >> 3;            // which of 4 edges in the quad
    int fl = (lane & 7) * 4;        // feature slot [fl..fl+3]
    int beg = g_rowptr[gw], end = g_rowptr[gw + 1];
    float4 acc = make_float4(0.f, 0.f, 0.f, 0.f);
#pragma unroll 1
    for (int e = beg + grp; e < end; e += 4) {
        EP p = g_ep[e];                                  // broadcast within 8-lane group
        const float4 xv = *(const float4*)(xin + p.s * 32 + fl);
        acc.x = fmaf(p.w, xv.x, acc.x);
        acc.y = fmaf(p.w, xv.y, acc.y);
        acc.z = fmaf(p.w, xv.z, acc.z);
        acc.w = fmaf(p.w, xv.w, acc.w);
    }
    // reduce the 4 edge-groups (lanes g*8+i share feature slot i)
#pragma unroll
    for (int off = 8; off <= 16; off <<= 1) {
        acc.x += __shfl_xor_sync(0xffffffffu, acc.x, off);
        acc.y += __shfl_xor_sync(0xffffffffu, acc.y, off);
        acc.z += __shfl_xor_sync(0xffffffffu, acc.z, off);
        acc.w += __shfl_xor_sync(0xffffffffu, acc.w, off);
    }
    if (lane < 8) {
        float* dst = g_TX[outsel] + gw * 32 + fl;
        if (SUB) {
            const float* prev = sel_ptr(prevsel, xext) + gw * 32 + fl;
            float4 pv = *(const float4*)prev;
            acc.x = 2.f * acc.x - pv.x;
            acc.y = 2.f * acc.y - pv.y;
            acc.z = 2.f * acc.z - pv.z;
            acc.w = 2.f * acc.w - pv.w;
        }
        *(float4*)dst = acc;
    }
}

// ---------------- fused Chebyshev GEMM + gates (+ head for MODE 1) ----------------
// MODE 0: write relu(h) to g_h.   MODE 1: fold head, write out[n].
template <int MODE>
__global__ void __launch_bounds__(128) k_gemm(const float* __restrict__ xext, int insel,
                                              int layer, const float* __restrict__ wc,
                                              float* __restrict__ out) {
    int w = threadIdx.x >> 5, lane = threadIdx.x & 31;
    int n0 = blockIdx.x * 16 + w * 4;
    const float* planes[5] = {sel_ptr(insel, xext), g_TX[0], g_TX[1], g_TX[2], g_TX[3]};
    const float4* Wj = g_Wj[layer];
    const float* bp = g_bp[layer];
    float b0 = bp[lane], b1 = bp[lane + 32], b2 = bp[lane + 64];
    ull acc[2][3];
#pragma unroll
    for (int tp = 0; tp < 2; tp++) {
        acc[tp][0] = pk2(b0, b0);
        acc[tp][1] = pk2(b1, b1);
        acc[tp][2] = pk2(b2, b2);
    }
#pragma unroll
    for (int k = 0; k < 5; k++) {
        const float* pl = planes[k];
#pragma unroll
        for (int jj = 0; jj < 32; jj += 4) {
            int j2 = (k * 32 + jj) >> 1;                 // two j-pairs per step
            // coalesced weight loads: lane-contiguous float4 ({wj,wj,wj+1,wj+1})
            ulonglong2 wA0 = *(const ulonglong2*)(Wj + (j2 + 0) * 96 + lane);
            ulonglong2 wB0 = *(const ulonglong2*)(Wj + (j2 + 1) * 96 + lane);
            ulonglong2 wA1 = *(const ulonglong2*)(Wj + (j2 + 0) * 96 + lane + 32);
            ulonglong2 wB1 = *(const ulonglong2*)(Wj + (j2 + 1) * 96 + lane + 32);
            ulonglong2 wA2 = *(const ulonglong2*)(Wj + (j2 + 0) * 96 + lane + 64);
            ulonglong2 wB2 = *(const ulonglong2*)(Wj + (j2 + 1) * 96 + lane + 64);
            // broadcast x loads (no lane dependence)
            float4 x0 = *(const float4*)(pl + (n0 + 0) * 32 + jj);
            float4 x1 = *(const float4*)(pl + (n0 + 1) * 32 + jj);
            float4 x2 = *(const float4*)(pl + (n0 + 2) * 32 + jj);
            float4 x3 = *(const float4*)(pl + (n0 + 3) * 32 + jj);
            ull xx0[4] = {pk2(x0.x, x1.x), pk2(x0.y, x1.y), pk2(x0.z, x1.z), pk2(x0.w, x1.w)};
            ull xx1[4] = {pk2(x2.x, x3.x), pk2(x2.y, x3.y), pk2(x2.z, x3.z), pk2(x2.w, x3.w)};
            ull w0[4] = {wA0.x, wA0.y, wB0.x, wB0.y};
            ull w1[4] = {wA1.x, wA1.y, wB1.x, wB1.y};
            ull w2[4] = {wA2.x, wA2.y, wB2.x, wB2.y};
#pragma unroll
            for (int c = 0; c < 4; c++) {
                acc[0][0] = ffma2(xx0[c], w0[c], acc[0][0]);
                acc[1][0] = ffma2(xx1[c], w0[c], acc[1][0]);
                acc[0][1] = ffma2(xx0[c], w1[c], acc[0][1]);
                acc[1][1] = ffma2(xx1[c], w1[c], acc[1][1]);
                acc[0][2] = ffma2(xx0[c], w2[c], acc[0][2]);
                acc[1][2] = ffma2(xx1[c], w2[c], acc[1][2]);
            }
        }
    }
    // ---- epilogue: gates (i, c, o), H=C=0 GConvLSTM ----
    float wc2 = wc[64 + lane];
    float we = 0.f, be = 0.f;
    if (MODE == 1) { we = g_weff[lane]; be = g_beff; }
#pragma unroll
    for (int tp = 0; tp < 2; tp++) {
        float iv[2], cv[2], ov[2];
        upk2(acc[tp][0], iv[0], iv[1]);
        upk2(acc[tp][1], cv[0], cv[1]);
        upk2(acc[tp][2], ov[0], ov[1]);
#pragma unroll
        for (int u = 0; u < 2; u++) {
            int n = n0 + tp * 2 + u;
            float I  = fsig(iv[u]);
            float Cn = I * ftanh(cv[u]);
            float O  = fsig(ov[u] + wc2 * Cn);
            float h  = fmaxf(O * ftanh(Cn), 0.f);
            if (MODE == 0) {
                g_h[n * 32 + lane] = h;
            } else {
                float v = h * we;
#pragma unroll
                for (int off = 16; off > 0; off >>= 1)
                    v += __shfl_xor_sync(0xffffffffu, v, off);
                if (lane == 0) out[n] = v + be;
            }
        }
    }
}

// ---------------- launch ----------------
extern "C" void kernel_launch(void* const* d_in, const int* in_sizes, int n_in,
                              void* d_out, int out_size) {
    const float* x     = (const float*)d_in[0];
    const int*   ei    = (const int*)d_in[1];
    const float* ew    = (const float*)d_in[2];
    const float* l1_Wx = (const float*)d_in[3];
    const float* l1_bx = (const float*)d_in[4];
    const float* l1_bh = (const float*)d_in[6];
    const float* l1_wc = (const float*)d_in[7];
    const float* l1_b  = (const float*)d_in[8];
    const float* l2_Wx = (const float*)d_in[9];
    const float* l2_bx = (const float*)d_in[10];
    const float* l2_bh = (const float*)d_in[12];
    const float* l2_wc = (const float*)d_in[13];
    const float* l2_b  = (const float*)d_in[14];
    const float* hw1   = (const float*)d_in[15];
    const float* hb1   = (const float*)d_in[16];
    const float* hw2   = (const float*)d_in[17];
    const float* hb2   = (const float*)d_in[18];
    const float* hw3   = (const float*)d_in[19];
    const float* hb3   = (const float*)d_in[20];
    const float* hw4   = (const float*)d_in[21];
    const float* hb4   = (const float*)d_in[22];
    float* out = (float*)d_out;

    const int NB_E = (NE + 255) / 256;   // 6250
    const int NB_W = 6250;               // 50000 warps / 8
    const int NB_G = NN / 16;            // 3125

    // graph normalization + CSR
    k_zero<<<NB_NODE, 256>>>();
    k_degree<<<NB_E, 256>>>(ei, ew);
    k_dinvsum<<<NB_NODE, 256>>>();
    k_scanb<<<1, 256>>>();
    k_rowptr<<<NB_NODE, 256>>>();
    k_scatter<<<NB_E, 256>>>(ei, ew);

    // weight packing + head folding
    k_prepw<<<30, 256>>>(l1_Wx, l1_bx, l1_bh, l1_b, 0);
    k_prepw<<<30, 256>>>(l2_Wx, l2_bx, l2_bh, l2_b, 1);
    k_headfold<<<1, 32>>>(hw1, hb1, hw2, hb2, hw3, hb3, hw4, hb4);

    // layer 1 (input = x, sel 9) -> g_h
    k_prop<false><<<NB_W, 256>>>(x, 9, -1, 0);
    k_prop<true ><<<NB_W, 256>>>(x, 0, 9, 1);
    k_prop<true ><<<NB_W, 256>>>(x, 1, 0, 2);
    k_prop<true ><<<NB_W, 256>>>(x, 2, 1, 3);
    k_gemm<0><<<NB_G, 128>>>(x, 9, 0, l1_wc, out);

    // layer 2 (input = g_h, sel 4) -> out (head fused)
    k_prop<false><<<NB_W, 256>>>(x, 4, -1, 0);
    k_prop<true ><<<NB_W, 256>>>(x, 0, 4, 1);
    k_prop<true ><<<NB_W, 256>>>(x, 1, 0, 2);
    k_prop<true ><<<NB_W, 256>>>(x, 2, 1, 3);
    k_gemm<1><<<NB_G, 128>>>(x, 4, 1, l2_wc, out);
}

// round 5
// speedup vs baseline: 1.4032x; 1.0602x over previous
#include <cuda_runtime.h>

#define NN 50000
#define NE 1600000
#define NB_NODE 196              // ceil(NN/256)

typedef unsigned long long ull;

struct __align__(8) EP { int s; float w; };

// ---------------- scratch (device globals; no allocations) ----------------
__device__ float g_degW[NN];
__device__ float g_dinv[NN];
__device__ int   g_cnt[NN];
__device__ int   g_bsum[NB_NODE];
__device__ int   g_boff[NB_NODE];
__device__ int   g_total;
__device__ int   g_rowptr[NN + 1];
__device__ int   g_wp[NN];
__device__ __align__(16) EP g_ep[NE];
__device__ __align__(16) float g_TX[4][NN * 32];       // Tx1..Tx4
__device__ __align__(16) float g_h[NN * 32];           // layer-1 output
__device__ __align__(16) float4 g_Wj[2][80 * 96];      // j-major splatted: [j/2][96] of {wj,wj,wj1,wj1}
__device__ float g_bp[2][96];                          // folded biases
__device__ __align__(16) float g_weff[32];             // folded head weight
__device__ float g_beff;

__device__ __forceinline__ const float* sel_ptr(int sel, const float* xext) {
    if (sel == 9) return xext;
    if (sel == 4) return g_h;
    return g_TX[sel];
}

__device__ __forceinline__ float fsig(float x) { return 1.f / (1.f + __expf(-x)); }
__device__ __forceinline__ float ftanh(float x) {
    x = fminf(fmaxf(x, -15.f), 15.f);
    float t = __expf(2.f * x);
    return (t - 1.f) / (t + 1.f);
}

// ---- packed f32x2 helpers (sm_103a FFMA2 is PTX-only) ----
__device__ __forceinline__ ull pk2(float lo, float hi) {
    ull r; asm("mov.b64 %0, {%1, %2};" : "=l"(r) : "f"(lo), "f"(hi)); return r;
}
__device__ __forceinline__ ull ffma2(ull a, ull b, ull c) {
    ull d; asm("fma.rn.f32x2 %0, %1, %2, %3;" : "=l"(d) : "l"(a), "l"(b), "l"(c)); return d;
}
__device__ __forceinline__ void upk2(ull v, float& lo, float& hi) {
    asm("mov.b64 {%0, %1}, %2;" : "=f"(lo), "=f"(hi) : "l"(v));
}

// ---------------- CSR build ----------------
__global__ void k_zero() {
    int i = blockIdx.x * blockDim.x + threadIdx.x;
    if (i < NN) { g_degW[i] = 0.f; g_cnt[i] = 0; }
}

__global__ void k_degree(const int* __restrict__ ei, const float* __restrict__ ew) {
    int e = blockIdx.x * blockDim.x + threadIdx.x;
    if (e >= NE) return;
    atomicAdd(&g_degW[ei[e]], ew[e]);       // weighted deg by SRC
    atomicAdd(&g_cnt[ei[NE + e]], 1);       // in-degree by DST
}

__global__ void k_dinvsum() {               // dinv + per-block count sums
    __shared__ int sh[256];
    int t = threadIdx.x;
    int i = blockIdx.x * 256 + t;
    int c = 0;
    if (i < NN) {
        float d = g_degW[i];
        g_dinv[i] = (d > 0.f) ? rsqrtf(fmaxf(d, 1e-12f)) : 0.f;
        c = g_cnt[i];
    }
    sh[t] = c;
    __syncthreads();
    for (int off = 128; off > 0; off >>= 1) {
        if (t < off) sh[t] += sh[t + off];
        __syncthreads();
    }
    if (t == 0) g_bsum[blockIdx.x] = sh[0];
}

__global__ void k_scanb() {                 // single block: scan block sums
    __shared__ int sh[256];
    int t = threadIdx.x;
    sh[t] = (t < NB_NODE) ? g_bsum[t] : 0;
    __syncthreads();
    for (int off = 1; off < 256; off <<= 1) {
        int v = 0;
        if (t >= off) v = sh[t - off];
        __syncthreads();
        sh[t] += v;
        __syncthreads();
    }
    if (t < NB_NODE) g_boff[t] = (t == 0) ? 0 : sh[t - 1];
    if (t == NB_NODE - 1) g_total = sh[t];
}

__global__ void k_rowptr() {                // per-block local scan + offset
    __shared__ int sh[256];
    int t = threadIdx.x;
    int i = blockIdx.x * 256 + t;
    int c = (i < NN) ? g_cnt[i] : 0;
    sh[t] = c;
    __syncthreads();
    for (int off = 1; off < 256; off <<= 1) {
        int v = 0;
        if (t >= off) v = sh[t - off];
        __syncthreads();
        sh[t] += v;
        __syncthreads();
    }
    if (i < NN) {
        int rp = g_boff[blockIdx.x] + sh[t] - c;
        g_rowptr[i] = rp;
        g_wp[i] = rp;
    }
    if (i == NN) g_rowptr[NN] = g_total;
}

__global__ void k_scatter(const int* __restrict__ ei, const float* __restrict__ ew) {
    int e = blockIdx.x * blockDim.x + threadIdx.x;
    if (e >= NE) return;
    int s = ei[e], d = ei[NE + e];
    int pos = atomicAdd(&g_wp[d], 1);
    EP p;
    p.s = s;
    p.w = -g_dinv[s] * ew[e] * g_dinv[d];
    g_ep[pos] = p;
}

// ---------------- weight / head prep ----------------
__global__ void k_prepw(const float* __restrict__ Wx, const float* __restrict__ bx,
                        const float* __restrict__ bh, const float* __restrict__ bb,
                        int layer) {
    int idx = blockIdx.x * blockDim.x + threadIdx.x;
    if (idx >= 80 * 96) return;
    int j2 = idx / 96, o = idx % 96;
    int gi = o >> 5, f = o & 31;
    int g = (gi == 0) ? 0 : ((gi == 1) ? 2 : 3);   // gates i, c, o (forget dead: C=0)
    float w[2];
#pragma unroll
    for (int u = 0; u < 2; u++) {
        int j = 2 * j2 + u;
        int k = j >> 5, jj = j & 31;
        w[u] = Wx[(((g * 5 + k) * 32) + jj) * 32 + f];
    }
    g_Wj[layer][idx] = make_float4(w[0], w[0], w[1], w[1]);
    if (j2 == 0) g_bp[layer][o] = bx[g * 32 + f] + bh[g * 32 + f] + bb[g * 32 + f];
}

__global__ void k_headfold(const float* __restrict__ hw1, const float* __restrict__ hb1,
                           const float* __restrict__ hw2, const float* __restrict__ hb2,
                           const float* __restrict__ hw3, const float* __restrict__ hb3,
                           const float* __restrict__ hw4, const float* __restrict__ hb4) {
    int r = threadIdx.x;   // 32 threads
    float t1r[16], t2r[8], t3r[4];
    for (int c = 0; c < 16; c++) t1r[c] = hw1[r * 16 + c];
    for (int c = 0; c < 8; c++) {
        float s = 0.f;
        for (int i = 0; i < 16; i++) s += t1r[i] * hw2[i * 8 + c];
        t2r[c] = s;
    }
    for (int c = 0; c < 4; c++) {
        float s = 0.f;
        for (int i = 0; i < 8; i++) s += t2r[i] * hw3[i * 4 + c];
        t3r[c] = s;
    }
    float we = 0.f;
    for (int i = 0; i < 4; i++) we += t3r[i] * hw4[i];
    g_weff[r] = we;
    if (r == 0) {
        float v2[8], v3[4];
        for (int c = 0; c < 8; c++) {
            float s = hb2[c];
            for (int i = 0; i < 16; i++) s += hb1[i] * hw2[i * 8 + c];
            v2[c] = s;
        }
        for (int c = 0; c < 4; c++) {
            float s = hb3[c];
            for (int i = 0; i < 8; i++) s += v2[i] * hw3[i * 4 + c];
            v3[c] = s;
        }
        float b = hb4[0];
        for (int i = 0; i < 4; i++) b += v3[i] * hw4[i];
        g_beff = b;
    }
}

// ---------------- sparse propagation: 4 edges/warp, 8 lanes x float4, 2x unroll ----------------
template <bool SUB>
__global__ void k_prop(const float* __restrict__ xext, int insel, int prevsel, int outsel) {
    int gw = (blockIdx.x * blockDim.x + threadIdx.x) >> 5;
    int lane = threadIdx.x & 31;
    if (gw >= NN) return;
    const float* xin = sel_ptr(insel, xext);
    int grp = lane >> 3;            // which of 4 edges in the quad
    int fl = (lane & 7) * 4;        // feature slot [fl..fl+3]
    int beg = g_rowptr[gw], end = g_rowptr[gw + 1];
    float4 acc = make_float4(0.f, 0.f, 0.f, 0.f);
    int e = beg + grp;
#pragma unroll 1
    for (; e + 4 < end; e += 8) {   // two quads in flight (MLP=2)
        EP p0 = g_ep[e];
        EP p1 = g_ep[e + 4];
        const float4 xa = *(const float4*)(xin + p0.s * 32 + fl);
        const float4 xb = *(const float4*)(xin + p1.s * 32 + fl);
        acc.x = fmaf(p0.w, xa.x, acc.x);
        acc.y = fmaf(p0.w, xa.y, acc.y);
        acc.z = fmaf(p0.w, xa.z, acc.z);
        acc.w = fmaf(p0.w, xa.w, acc.w);
        acc.x = fmaf(p1.w, xb.x, acc.x);
        acc.y = fmaf(p1.w, xb.y, acc.y);
        acc.z = fmaf(p1.w, xb.z, acc.z);
        acc.w = fmaf(p1.w, xb.w, acc.w);
    }
    if (e < end) {
        EP p = g_ep[e];
        const float4 xv = *(const float4*)(xin + p.s * 32 + fl);
        acc.x = fmaf(p.w, xv.x, acc.x);
        acc.y = fmaf(p.w, xv.y, acc.y);
        acc.z = fmaf(p.w, xv.z, acc.z);
        acc.w = fmaf(p.w, xv.w, acc.w);
    }
    // reduce the 4 edge-groups
#pragma unroll
    for (int off = 8; off <= 16; off <<= 1) {
        acc.x += __shfl_xor_sync(0xffffffffu, acc.x, off);
        acc.y += __shfl_xor_sync(0xffffffffu, acc.y, off);
        acc.z += __shfl_xor_sync(0xffffffffu, acc.z, off);
        acc.w += __shfl_xor_sync(0xffffffffu, acc.w, off);
    }
    if (lane < 8) {
        float* dst = g_TX[outsel] + gw * 32 + fl;
        if (SUB) {
            const float* prev = sel_ptr(prevsel, xext) + gw * 32 + fl;
            float4 pv = *(const float4*)prev;
            acc.x = 2.f * acc.x - pv.x;
            acc.y = 2.f * acc.y - pv.y;
            acc.z = 2.f * acc.z - pv.z;
            acc.w = 2.f * acc.w - pv.w;
        }
        *(float4*)dst = acc;
    }
}

// ---------------- fused Chebyshev GEMM + gates (+ head), 16 nodes/warp ----------------
// MODE 0: write relu(h) to g_h.   MODE 1: fold head, write out[n].
template <int MODE>
__global__ void __launch_bounds__(128) k_gemm(const float* __restrict__ xext, int insel,
                                              int layer, const float* __restrict__ wc,
                                              float* __restrict__ out) {
    int w = threadIdx.x >> 5, lane = threadIdx.x & 31;
    int n0 = (blockIdx.x * 4 + w) * 16;
    if (n0 >= NN) return;
    const float* planes[5] = {sel_ptr(insel, xext), g_TX[0], g_TX[1], g_TX[2], g_TX[3]};
    const float4* Wj = g_Wj[layer];
    const float* bp = g_bp[layer];
    float b0 = bp[lane], b1 = bp[lane + 32], b2 = bp[lane + 64];
    ull acc[8][3];                               // 8 node-pairs x 3 gate-outputs
#pragma unroll
    for (int p = 0; p < 8; p++) {
        acc[p][0] = pk2(b0, b0);
        acc[p][1] = pk2(b1, b1);
        acc[p][2] = pk2(b2, b2);
    }
#pragma unroll
    for (int k = 0; k < 5; k++) {
        const float* pl = planes[k];
#pragma unroll
        for (int jj = 0; jj < 32; jj += 4) {
            int j2 = (k * 32 + jj) >> 1;
            const float4* Wp = Wj + j2 * 96 + lane;
            // weights for j = kk*32+jj .. +3, outputs (lane, lane+32, lane+64); coalesced
            ulonglong2 wA0 = *(const ulonglong2*)(Wp);
            ulonglong2 wB0 = *(const ulonglong2*)(Wp + 96);
            ulonglong2 wA1 = *(const ulonglong2*)(Wp + 32);
            ulonglong2 wB1 = *(const ulonglong2*)(Wp + 96 + 32);
            ulonglong2 wA2 = *(const ulonglong2*)(Wp + 64);
            ulonglong2 wB2 = *(const ulonglong2*)(Wp + 96 + 64);
            ull w0[4] = {wA0.x, wA0.y, wB0.x, wB0.y};
            ull w1[4] = {wA1.x, wA1.y, wB1.x, wB1.y};
            ull w2[4] = {wA2.x, wA2.y, wB2.x, wB2.y};
            // 8 node-pairs consumed against the same weight registers
#pragma unroll
            for (int p = 0; p < 8; p++) {
                const float4 xa = *(const float4*)(pl + (n0 + 2 * p) * 32 + jj);
                const float4 xb = *(const float4*)(pl + (n0 + 2 * p + 1) * 32 + jj);
                ull q0 = pk2(xa.x, xb.x);
                ull q1 = pk2(xa.y, xb.y);
                ull q2 = pk2(xa.z, xb.z);
                ull q3 = pk2(xa.w, xb.w);
                acc[p][0] = ffma2(q0, w0[0], acc[p][0]);
                acc[p][1] = ffma2(q0, w1[0], acc[p][1]);
                acc[p][2] = ffma2(q0, w2[0], acc[p][2]);
                acc[p][0] = ffma2(q1, w0[1], acc[p][0]);
                acc[p][1] = ffma2(q1, w1[1], acc[p][1]);
                acc[p][2] = ffma2(q1, w2[1], acc[p][2]);
                acc[p][0] = ffma2(q2, w0[2], acc[p][0]);
                acc[p][1] = ffma2(q2, w1[2], acc[p][1]);
                acc[p][2] = ffma2(q2, w2[2], acc[p][2]);
                acc[p][0] = ffma2(q3, w0[3], acc[p][0]);
                acc[p][1] = ffma2(q3, w1[3], acc[p][1]);
                acc[p][2] = ffma2(q3, w2[3], acc[p][2]);
            }
        }
    }
    // ---- epilogue: gates (i, c, o), H=C=0 GConvLSTM ----
    float wc2 = wc[64 + lane];
    float we = 0.f, be = 0.f;
    if (MODE == 1) { we = g_weff[lane]; be = g_beff; }
#pragma unroll
    for (int p = 0; p < 8; p++) {
        float iv[2], cv[2], ov[2];
        upk2(acc[p][0], iv[0], iv[1]);
        upk2(acc[p][1], cv[0], cv[1]);
        upk2(acc[p][2], ov[0], ov[1]);
#pragma unroll
        for (int u = 0; u < 2; u++) {
            int n = n0 + 2 * p + u;
            float I  = fsig(iv[u]);
            float Cn = I * ftanh(cv[u]);
            float O  = fsig(ov[u] + wc2 * Cn);
            float h  = fmaxf(O * ftanh(Cn), 0.f);
            if (MODE == 0) {
                g_h[n * 32 + lane] = h;
            } else {
                float v = h * we;
#pragma unroll
                for (int off = 16; off > 0; off >>= 1)
                    v += __shfl_xor_sync(0xffffffffu, v, off);
                if (lane == 0) out[n] = v + be;
            }
        }
    }
}

// ---------------- launch ----------------
extern "C" void kernel_launch(void* const* d_in, const int* in_sizes, int n_in,
                              void* d_out, int out_size) {
    const float* x     = (const float*)d_in[0];
    const int*   ei    = (const int*)d_in[1];
    const float* ew    = (const float*)d_in[2];
    const float* l1_Wx = (const float*)d_in[3];
    const float* l1_bx = (const float*)d_in[4];
    const float* l1_bh = (const float*)d_in[6];
    const float* l1_wc = (const float*)d_in[7];
    const float* l1_b  = (const float*)d_in[8];
    const float* l2_Wx = (const float*)d_in[9];
    const float* l2_bx = (const float*)d_in[10];
    const float* l2_bh = (const float*)d_in[12];
    const float* l2_wc = (const float*)d_in[13];
    const float* l2_b  = (const float*)d_in[14];
    const float* hw1   = (const float*)d_in[15];
    const float* hb1   = (const float*)d_in[16];
    const float* hw2   = (const float*)d_in[17];
    const float* hb2   = (const float*)d_in[18];
    const float* hw3   = (const float*)d_in[19];
    const float* hb3   = (const float*)d_in[20];
    const float* hw4   = (const float*)d_in[21];
    const float* hb4   = (const float*)d_in[22];
    float* out = (float*)d_out;

    const int NB_E = (NE + 255) / 256;   // 6250
    const int NB_W = 6250;               // 50000 warps / 8
    const int NB_G = (NN + 63) / 64;     // 782 (16 nodes/warp, 4 warps/block)

    // graph normalization + CSR
    k_zero<<<NB_NODE, 256>>>();
    k_degree<<<NB_E, 256>>>(ei, ew);
    k_dinvsum<<<NB_NODE, 256>>>();
    k_scanb<<<1, 256>>>();
    k_rowptr<<<NB_NODE, 256>>>();
    k_scatter<<<NB_E, 256>>>(ei, ew);

    // weight packing + head folding
    k_prepw<<<30, 256>>>(l1_Wx, l1_bx, l1_bh, l1_b, 0);
    k_prepw<<<30, 256>>>(l2_Wx, l2_bx, l2_bh, l2_b, 1);
    k_headfold<<<1, 32>>>(hw1, hb1, hw2, hb2, hw3, hb3, hw4, hb4);

    // layer 1 (input = x, sel 9) -> g_h
    k_prop<false><<<NB_W, 256>>>(x, 9, -1, 0);
    k_prop<true ><<<NB_W, 256>>>(x, 0, 9, 1);
    k_prop<true ><<<NB_W, 256>>>(x, 1, 0, 2);
    k_prop<true ><<<NB_W, 256>>>(x, 2, 1, 3);
    k_gemm<0><<<NB_G, 128>>>(x, 9, 0, l1_wc, out);

    // layer 2 (input = g_h, sel 4) -> out (head fused)
    k_prop<false><<<NB_W, 256>>>(x, 4, -1, 0);
    k_prop<true ><<<NB_W, 256>>>(x, 0, 4, 1);
    k_prop<true ><<<NB_W, 256>>>(x, 1, 0, 2);
    k_prop<true ><<<NB_W, 256>>>(x, 2, 1, 3);
    k_gemm<1><<<NB_G, 128>>>(x, 4, 1, l2_wc, out);
}